// round 6
// baseline (speedup 1.0000x reference)
#include <cuda_runtime.h>
#include <cuda_bf16.h>
#include <cstdint>

#define B_  16
#define C_  256
#define N_  1024
#define NG  4
#define GC  64

typedef __nv_bfloat16 bf16;

// ---- scratch (static device globals) ----
__device__ bf16  g_hT[(size_t)B_ * N_ * C_];   // groupnorm out, [b][n][c]
__device__ bf16  g_q [(size_t)B_ * N_ * C_];   // [b][n][d], pre-scaled by 1/16
__device__ bf16  g_k [(size_t)B_ * N_ * C_];
__device__ bf16  g_vt[(size_t)B_ * C_ * N_];   // V transposed: [b][d][m]
__device__ bf16  g_p [(size_t)B_ * N_ * N_];   // probs bf16 [query][key]
__device__ bf16  g_wq[C_ * C_];
__device__ bf16  g_wk[C_ * C_];
__device__ bf16  g_wv[C_ * C_];
__device__ float g_red[B_ * NG][8][2];         // groupnorm partial sums

// ---------------------------------------------------------------------------
// helpers (family-safe PTX: ldmatrix / mma.sync / cp.async)
// ---------------------------------------------------------------------------
__device__ __forceinline__ uint32_t smem_u32(const void* p) {
    return (uint32_t)__cvta_generic_to_shared(p);
}
__device__ __forceinline__ void ldsm4(uint32_t* r, uint32_t addr) {
    asm volatile("ldmatrix.sync.aligned.m8n8.x4.shared.b16 {%0,%1,%2,%3}, [%4];"
                 : "=r"(r[0]), "=r"(r[1]), "=r"(r[2]), "=r"(r[3]) : "r"(addr));
}
__device__ __forceinline__ void mma16816(float* c, const uint32_t* a, const uint32_t* b) {
    asm volatile(
        "mma.sync.aligned.m16n8k16.row.col.f32.bf16.bf16.f32 "
        "{%0,%1,%2,%3}, {%4,%5,%6,%7}, {%8,%9}, {%0,%1,%2,%3};"
        : "+f"(c[0]), "+f"(c[1]), "+f"(c[2]), "+f"(c[3])
        : "r"(a[0]), "r"(a[1]), "r"(a[2]), "r"(a[3]), "r"(b[0]), "r"(b[1]));
}
__device__ __forceinline__ void cp16(uint32_t dst, const void* src) {
    asm volatile("cp.async.cg.shared.global [%0], [%1], 16;" :: "r"(dst), "l"(src));
}
__device__ __forceinline__ void cp_commit() { asm volatile("cp.async.commit_group;" ::: "memory"); }
__device__ __forceinline__ void cp_wait0()  { asm volatile("cp.async.wait_group 0;" ::: "memory"); }
__device__ __forceinline__ void cp_wait1()  { asm volatile("cp.async.wait_group 1;" ::: "memory"); }

#define KT      32
#define STRIDE  40

// ---------------------------------------------------------------------------
// Big-tile GEMM: CTA tile 128(M) x 256(N), 8 warps (warp tile 64x64), KT=32,
// 3-stage cp.async. acc[4][8][4] = 128 regs. Tensor-bound by design:
// smem reads/tile = 64KB (512 cyc) < tensor 1024 cyc.
// ---------------------------------------------------------------------------
#define A_TB   (128 * STRIDE * 2)       // 10240 B
#define B_TB   (256 * STRIDE * 2)       // 20480 B
#define STG2   (A_TB + B_TB)            // 30720 B per stage
#define NST    3
#define G2_SMEM (NST * STG2)            // 92160 B

__device__ __forceinline__ void copy_tile2(const bf16* A, int lda, const bf16* B, int ldb,
                                           uint32_t sA, uint32_t sB, int k0, int tid) {
    #pragma unroll
    for (int c = 0; c < 2; c++) {        // A: 512 chunks of 16B
        int id = tid + 256 * c;
        int row = id >> 2, col = (id & 3) * 8;
        cp16(sA + (uint32_t)(row * STRIDE + col) * 2, A + (size_t)row * lda + k0 + col);
    }
    #pragma unroll
    for (int c = 0; c < 4; c++) {        // B: 1024 chunks of 16B
        int id = tid + 256 * c;
        int row = id >> 2, col = (id & 3) * 8;
        cp16(sB + (uint32_t)(row * STRIDE + col) * 2, B + (size_t)row * ldb + k0 + col);
    }
    cp_commit();
}

__device__ __forceinline__ void gemm_big(const bf16* A, int lda, const bf16* B, int ldb,
                                         int T, char* smem, float acc[4][8][4], int tid) {
    int lane = tid & 31, wid = tid >> 5;
    int wm = wid & 1, wn = wid >> 1;     // 2 x 4 warp grid
    uint32_t base = smem_u32(smem);

    #pragma unroll
    for (int s = 0; s < NST - 1; s++)
        copy_tile2(A, lda, B, ldb, base + s * STG2, base + s * STG2 + A_TB, s * KT, tid);

    int ar = lane & 15, ak = (lane >> 4) * 8;
    for (int t = 0; t < T; t++) {
        cp_wait1();              // tile t resident (allow 1 younger pending)
        __syncthreads();
        int nxt = t + NST - 1;
        if (nxt < T) {
            uint32_t sb = base + (nxt % NST) * STG2;
            copy_tile2(A, lda, B, ldb, sb, sb + A_TB, nxt * KT, tid);
        } else {
            cp_commit();
        }
        uint32_t aB = base + (t % NST) * STG2;
        uint32_t bB = aB + A_TB;

        #pragma unroll
        for (int kk = 0; kk < 2; kk++) {
            uint32_t af[4][4];
            #pragma unroll
            for (int mt = 0; mt < 4; mt++)
                ldsm4(af[mt], aB + (uint32_t)((wm * 64 + mt * 16 + ar) * STRIDE + kk * 16 + ak) * 2);
            uint32_t bfm[8][2];
            #pragma unroll
            for (int np = 0; np < 4; np++) {
                uint32_t r[4];
                ldsm4(r, bB + (uint32_t)((wn * 64 + np * 16 + ar) * STRIDE + kk * 16 + ak) * 2);
                bfm[np * 2][0] = r[0];     bfm[np * 2][1] = r[2];
                bfm[np * 2 + 1][0] = r[1]; bfm[np * 2 + 1][1] = r[3];
            }
            #pragma unroll
            for (int mt = 0; mt < 4; mt++)
                #pragma unroll
                for (int nt = 0; nt < 8; nt++)
                    mma16816(acc[mt][nt], af[mt], bfm[nt]);
        }
    }
}

// ---------------------------------------------------------------------------
// 0. weights fp32 -> bf16
// ---------------------------------------------------------------------------
__global__ __launch_bounds__(256) void prep_kernel(const float* __restrict__ Wq,
                                                   const float* __restrict__ Wk,
                                                   const float* __restrict__ Wv) {
    int i = blockIdx.x * 256 + threadIdx.x;
    float4 a; uint2 u; __nv_bfloat162 h0, h1;
    a = reinterpret_cast<const float4*>(Wq)[i];
    h0 = __floats2bfloat162_rn(a.x, a.y); h1 = __floats2bfloat162_rn(a.z, a.w);
    u.x = *reinterpret_cast<uint32_t*>(&h0); u.y = *reinterpret_cast<uint32_t*>(&h1);
    reinterpret_cast<uint2*>(g_wq)[i] = u;
    a = reinterpret_cast<const float4*>(Wk)[i];
    h0 = __floats2bfloat162_rn(a.x, a.y); h1 = __floats2bfloat162_rn(a.z, a.w);
    u.x = *reinterpret_cast<uint32_t*>(&h0); u.y = *reinterpret_cast<uint32_t*>(&h1);
    reinterpret_cast<uint2*>(g_wk)[i] = u;
    a = reinterpret_cast<const float4*>(Wv)[i];
    h0 = __floats2bfloat162_rn(a.x, a.y); h1 = __floats2bfloat162_rn(a.z, a.w);
    u.x = *reinterpret_cast<uint32_t*>(&h0); u.y = *reinterpret_cast<uint32_t*>(&h1);
    reinterpret_cast<uint2*>(g_wv)[i] = u;
}

// ---------------------------------------------------------------------------
// 1a. GroupNorm stats
// ---------------------------------------------------------------------------
__global__ __launch_bounds__(256) void gn_stats_kernel(const float* __restrict__ x) {
    int s = blockIdx.x, bg = blockIdx.y;
    const float* xp = x + (size_t)bg * GC * N_ + (size_t)s * 8192;
    float sum = 0.f, ss = 0.f;
    #pragma unroll
    for (int i = 0; i < 8; i++) {
        float4 v = reinterpret_cast<const float4*>(xp)[threadIdx.x + i * 256];
        sum += v.x + v.y + v.z + v.w;
        ss  += v.x * v.x + v.y * v.y + v.z * v.z + v.w * v.w;
    }
    __shared__ float sh1[256], sh2[256];
    sh1[threadIdx.x] = sum; sh2[threadIdx.x] = ss;
    __syncthreads();
    for (int o = 128; o > 0; o >>= 1) {
        if (threadIdx.x < o) {
            sh1[threadIdx.x] += sh1[threadIdx.x + o];
            sh2[threadIdx.x] += sh2[threadIdx.x + o];
        }
        __syncthreads();
    }
    if (threadIdx.x == 0) {
        g_red[bg][s][0] = sh1[0];
        g_red[bg][s][1] = sh2[0];
    }
}

// ---------------------------------------------------------------------------
// 1b. GroupNorm apply + transpose: x[b][c][n] -> hT[b][n][c] bf16
// ---------------------------------------------------------------------------
__global__ __launch_bounds__(256) void gn_apply_kernel(const float* __restrict__ x,
                                                       const float* __restrict__ gamma,
                                                       const float* __restrict__ beta) {
    int ns = blockIdx.x, g = blockIdx.y, b = blockIdx.z;
    int bg = b * NG + g;
    float sum = 0.f, ss = 0.f;
    #pragma unroll
    for (int i = 0; i < 8; i++) { sum += g_red[bg][i][0]; ss += g_red[bg][i][1]; }
    const float inv_n = 1.0f / (GC * N_);
    float mean = sum * inv_n;
    float var  = ss * inv_n - mean * mean;
    float rstd = rsqrtf(var + 1e-5f);

    const float* xp = x + (size_t)bg * GC * N_;
    bf16* out = g_hT + (size_t)b * N_ * C_ + g * GC;
    __shared__ float tile[32 * 65];
    int tid = threadIdx.x;
    int nbase = ns * 128;
    for (int n0 = nbase; n0 < nbase + 128; n0 += 32) {
        for (int e = tid; e < GC * 32; e += 256) {
            int c = e >> 5, n = e & 31;
            float v = (xp[(size_t)c * N_ + n0 + n] - mean) * rstd;
            v = v * __ldg(&gamma[g * GC + c]) + __ldg(&beta[g * GC + c]);
            tile[n * 65 + c] = v;
        }
        __syncthreads();
        {
            int n = tid >> 3, u = tid & 7;
            uint32_t pk[4];
            #pragma unroll
            for (int j = 0; j < 4; j++) {
                __nv_bfloat162 h = __floats2bfloat162_rn(tile[n * 65 + u * 8 + 2 * j],
                                                         tile[n * 65 + u * 8 + 2 * j + 1]);
                pk[j] = *reinterpret_cast<uint32_t*>(&h);
            }
            *reinterpret_cast<uint4*>(out + (size_t)(n0 + n) * C_ + u * 8) =
                *reinterpret_cast<uint4*>(pk);
        }
        __syncthreads();
    }
}

// ---------------------------------------------------------------------------
// 2. QKV (CTA tile 128 tokens x 256 channels, full d per CTA)
//    mi=0 -> q (x 1/16), mi=1 -> k, mi=2 -> Vt.
// ---------------------------------------------------------------------------
__global__ __launch_bounds__(256) void qkv_kernel(const float* __restrict__ bq,
                                                  const float* __restrict__ bk,
                                                  const float* __restrict__ bv) {
    extern __shared__ __align__(16) char dsm[];
    int tid = threadIdx.x;
    int mi = blockIdx.y % 3, b = blockIdx.y / 3;
    int m0 = blockIdx.x * 128;
    const bf16* A  = g_hT + (size_t)b * N_ * C_ + (size_t)m0 * C_;
    const bf16* Bm = (mi == 0 ? g_wq : mi == 1 ? g_wk : g_wv);
    float acc[4][8][4] = {};
    gemm_big(A, C_, Bm, C_, C_ / KT, dsm, acc, tid);

    int lane = tid & 31, wid = tid >> 5;
    int wm = wid & 1, wn = wid >> 1;
    int quad = lane >> 2, qt = lane & 3;
    const float* bias = (mi == 0) ? bq : (mi == 1) ? bk : bv;

    if (mi < 2) {
        bf16* out = ((mi == 0) ? g_q : g_k) + (size_t)b * N_ * C_;
        float scale = (mi == 0) ? 0.0625f : 1.0f;
        #pragma unroll
        for (int mt = 0; mt < 4; mt++) {
            int r0 = m0 + wm * 64 + mt * 16 + quad;
            #pragma unroll
            for (int nt = 0; nt < 8; nt++) {
                int d = wn * 64 + nt * 8 + qt * 2;
                float b0 = __ldg(&bias[d]), b1 = __ldg(&bias[d + 1]);
                __nv_bfloat162 h0 = __floats2bfloat162_rn((acc[mt][nt][0] + b0) * scale,
                                                          (acc[mt][nt][1] + b1) * scale);
                __nv_bfloat162 h1 = __floats2bfloat162_rn((acc[mt][nt][2] + b0) * scale,
                                                          (acc[mt][nt][3] + b1) * scale);
                *reinterpret_cast<uint32_t*>(out + (size_t)r0 * C_ + d) =
                    *reinterpret_cast<uint32_t*>(&h0);
                *reinterpret_cast<uint32_t*>(out + (size_t)(r0 + 8) * C_ + d) =
                    *reinterpret_cast<uint32_t*>(&h1);
            }
        }
    } else {
        // Vt: stage transposed [d 256][m 128] in smem (stride 136), coalesced write
        bf16* st = reinterpret_cast<bf16*>(dsm);
        __syncthreads();
        #pragma unroll
        for (int mt = 0; mt < 4; mt++) {
            int ml = wm * 64 + mt * 16 + quad;
            #pragma unroll
            for (int nt = 0; nt < 8; nt++) {
                int dl = wn * 64 + nt * 8 + qt * 2;
                float b0 = __ldg(&bias[dl]), b1 = __ldg(&bias[dl + 1]);
                st[dl * 136 + ml]           = __float2bfloat16_rn(acc[mt][nt][0] + b0);
                st[(dl + 1) * 136 + ml]     = __float2bfloat16_rn(acc[mt][nt][1] + b1);
                st[dl * 136 + ml + 8]       = __float2bfloat16_rn(acc[mt][nt][2] + b0);
                st[(dl + 1) * 136 + ml + 8] = __float2bfloat16_rn(acc[mt][nt][3] + b1);
            }
        }
        __syncthreads();
        bf16* outv = g_vt + (size_t)b * C_ * N_;
        #pragma unroll
        for (int c = 0; c < 16; c++) {
            int id = tid + 256 * c;          // 4096 chunks of 16B
            int d = id >> 4, ch = (id & 15) * 8;
            *reinterpret_cast<uint4*>(outv + (size_t)d * N_ + m0 + ch) =
                *reinterpret_cast<uint4*>(st + d * 136 + ch);
        }
    }
}

// ---------------------------------------------------------------------------
// 3. FUSED scores+softmax, 512 threads (as R5)
// ---------------------------------------------------------------------------
#define FS_STAGE ((1024 + 32) * STRIDE * 2)
#define FS_SMEM  (2 * FS_STAGE)

__device__ __forceinline__ void fs_copy(const bf16* Q, const bf16* K,
                                        uint32_t sK, uint32_t sQ, int k0, int tid) {
    #pragma unroll
    for (int i = 0; i < 9; i++) {
        int id = tid + 512 * i;
        if (id < 4096) {
            int row = id >> 2, col = (id & 3) * 8;
            cp16(sK + (uint32_t)(row * STRIDE + col) * 2, K + (size_t)row * C_ + k0 + col);
        } else if (id < 4224) {
            int q = id - 4096;
            int row = q >> 2, col = (q & 3) * 8;
            cp16(sQ + (uint32_t)(row * STRIDE + col) * 2, Q + (size_t)row * C_ + k0 + col);
        }
    }
    cp_commit();
}

__global__ __launch_bounds__(512, 1) void score_softmax_kernel() {
    extern __shared__ __align__(16) char dsm[];
    int tid = threadIdx.x;
    int lane = tid & 31, wid = tid >> 5;
    int quad = lane >> 2, qt = lane & 3;
    int wn = wid & 7, wq = wid >> 3;
    int b = blockIdx.y, m0 = blockIdx.x * 32;

    const bf16* Q = g_q + ((size_t)b * N_ + m0) * C_;
    const bf16* K = g_k + (size_t)b * N_ * C_;

    uint32_t base = smem_u32(dsm);
    uint32_t sK0 = base, sQ0 = base + 1024 * STRIDE * 2;
    uint32_t sK1 = base + FS_STAGE, sQ1 = sK1 + 1024 * STRIDE * 2;

    float acc[16][4] = {};

    fs_copy(Q, K, sK0, sQ0, 0, tid);
    int ar = lane & 15, ak = (lane >> 4) * 8;
    const int T = C_ / KT;  // 8
    for (int t = 0; t < T; t++) {
        cp_wait0();
        __syncthreads();
        if (t + 1 < T)
            fs_copy(Q, K, (t & 1) ? sK0 : sK1, (t & 1) ? sQ0 : sQ1, (t + 1) * KT, tid);
        else
            cp_commit();
        uint32_t kB = (t & 1) ? sK1 : sK0;
        uint32_t qB = (t & 1) ? sQ1 : sQ0;

        #pragma unroll
        for (int kk = 0; kk < 2; kk++) {
            uint32_t af[4];
            ldsm4(af, qB + (uint32_t)((wq * 16 + ar) * STRIDE + kk * 16 + ak) * 2);
            #pragma unroll
            for (int np = 0; np < 8; np++) {
                uint32_t r[4];
                ldsm4(r, kB + (uint32_t)((wn * 128 + np * 16 + ar) * STRIDE + kk * 16 + ak) * 2);
                uint32_t b0[2] = {r[0], r[2]};
                uint32_t b1[2] = {r[1], r[3]};
                mma16816(acc[np * 2],     af, b0);
                mma16816(acc[np * 2 + 1], af, b1);
            }
        }
    }

    float* red  = reinterpret_cast<float*>(dsm);
    float* red2 = red + 32 * 8;

    float rmax[2] = {-1e30f, -1e30f};
    #pragma unroll
    for (int nt = 0; nt < 16; nt++) {
        rmax[0] = fmaxf(rmax[0], fmaxf(acc[nt][0], acc[nt][1]));
        rmax[1] = fmaxf(rmax[1], fmaxf(acc[nt][2], acc[nt][3]));
    }
    #pragma unroll
    for (int h = 0; h < 2; h++) {
        rmax[h] = fmaxf(rmax[h], __shfl_xor_sync(0xffffffffu, rmax[h], 1));
        rmax[h] = fmaxf(rmax[h], __shfl_xor_sync(0xffffffffu, rmax[h], 2));
    }
    if (qt == 0) {
        red[(wq * 16 + quad) * 8 + wn]     = rmax[0];
        red[(wq * 16 + 8 + quad) * 8 + wn] = rmax[1];
    }
    __syncthreads();
    float M[2];
    #pragma unroll
    for (int h = 0; h < 2; h++) {
        float m = -1e30f;
        #pragma unroll
        for (int w8 = 0; w8 < 8; w8++) m = fmaxf(m, red[(wq * 16 + h * 8 + quad) * 8 + w8]);
        M[h] = m;
    }

    float rsum[2] = {0.f, 0.f};
    #pragma unroll
    for (int nt = 0; nt < 16; nt++) {
        acc[nt][0] = __expf(acc[nt][0] - M[0]);
        acc[nt][1] = __expf(acc[nt][1] - M[0]);
        acc[nt][2] = __expf(acc[nt][2] - M[1]);
        acc[nt][3] = __expf(acc[nt][3] - M[1]);
        rsum[0] += acc[nt][0] + acc[nt][1];
        rsum[1] += acc[nt][2] + acc[nt][3];
    }
    #pragma unroll
    for (int h = 0; h < 2; h++) {
        rsum[h] += __shfl_xor_sync(0xffffffffu, rsum[h], 1);
        rsum[h] += __shfl_xor_sync(0xffffffffu, rsum[h], 2);
    }
    if (qt == 0) {
        red2[(wq * 16 + quad) * 8 + wn]     = rsum[0];
        red2[(wq * 16 + 8 + quad) * 8 + wn] = rsum[1];
    }
    __syncthreads();
    float inv[2];
    #pragma unroll
    for (int h = 0; h < 2; h++) {
        float s = 0.f;
        #pragma unroll
        for (int w8 = 0; w8 < 8; w8++) s += red2[(wq * 16 + h * 8 + quad) * 8 + w8];
        inv[h] = 1.0f / s;
    }

    bf16* P = g_p + (size_t)b * N_ * N_;
    int r0 = m0 + wq * 16 + quad;
    #pragma unroll
    for (int nt = 0; nt < 16; nt++) {
        int cc = wn * 128 + nt * 8 + qt * 2;
        __nv_bfloat162 h0 = __floats2bfloat162_rn(acc[nt][0] * inv[0], acc[nt][1] * inv[0]);
        __nv_bfloat162 h1 = __floats2bfloat162_rn(acc[nt][2] * inv[1], acc[nt][3] * inv[1]);
        *reinterpret_cast<uint32_t*>(P + (size_t)r0 * N_ + cc) = *reinterpret_cast<uint32_t*>(&h0);
        *reinterpret_cast<uint32_t*>(P + (size_t)(r0 + 8) * N_ + cc) = *reinterpret_cast<uint32_t*>(&h1);
    }
}

// ---------------------------------------------------------------------------
// 5. PV as O^T (CTA tile 128 channels x 256 tokens):
//    out[b][c][n] = sum_m Vt[b][c][m] * P[b][n][m] + x[b][c][n]
// ---------------------------------------------------------------------------
__global__ __launch_bounds__(256) void pv_kernel(const float* __restrict__ x,
                                                 float* __restrict__ outp) {
    extern __shared__ __align__(16) char dsm[];
    int tid = threadIdx.x;
    int b = blockIdx.z;
    int n0 = blockIdx.x * 256;   // token tile
    int m0 = blockIdx.y * 128;   // channel tile
    const bf16* A  = g_vt + (size_t)b * C_ * N_ + (size_t)m0 * N_;
    const bf16* Bm = g_p  + (size_t)b * N_ * N_ + (size_t)n0 * N_;
    float acc[4][8][4] = {};
    gemm_big(A, N_, Bm, N_, N_ / KT, dsm, acc, tid);

    int lane = tid & 31, wid = tid >> 5;
    int wm = wid & 1, wn = wid >> 1;
    int quad = lane >> 2, qt = lane & 3;
    #pragma unroll
    for (int mt = 0; mt < 4; mt++) {
        int cg = m0 + wm * 64 + mt * 16 + quad;
        #pragma unroll
        for (int nt = 0; nt < 8; nt++) {
            int ng = n0 + wn * 64 + nt * 8 + qt * 2;
            size_t base = ((size_t)b * C_ + cg) * N_ + ng;
            float2 xv = *reinterpret_cast<const float2*>(x + base);
            *reinterpret_cast<float2*>(outp + base) =
                make_float2(acc[mt][nt][0] + xv.x, acc[mt][nt][1] + xv.y);
            size_t base8 = base + (size_t)8 * N_;
            float2 xv8 = *reinterpret_cast<const float2*>(x + base8);
            *reinterpret_cast<float2*>(outp + base8) =
                make_float2(acc[mt][nt][2] + xv8.x, acc[mt][nt][3] + xv8.y);
        }
    }
}

// ---------------------------------------------------------------------------
extern "C" void kernel_launch(void* const* d_in, const int* in_sizes, int n_in,
                              void* d_out, int out_size) {
    const float* x     = (const float*)d_in[0];
    const float* Wq    = (const float*)d_in[1];
    const float* bq    = (const float*)d_in[2];
    const float* Wk    = (const float*)d_in[3];
    const float* bk    = (const float*)d_in[4];
    const float* Wv    = (const float*)d_in[5];
    const float* bv    = (const float*)d_in[6];
    const float* gamma = (const float*)d_in[7];
    const float* beta  = (const float*)d_in[8];
    float* out = (float*)d_out;

    cudaFuncSetAttribute(qkv_kernel, cudaFuncAttributeMaxDynamicSharedMemorySize, G2_SMEM);
    cudaFuncSetAttribute(pv_kernel, cudaFuncAttributeMaxDynamicSharedMemorySize, G2_SMEM);
    cudaFuncSetAttribute(score_softmax_kernel, cudaFuncAttributeMaxDynamicSharedMemorySize, FS_SMEM);

    prep_kernel<<<64, 256>>>(Wq, Wk, Wv);
    gn_stats_kernel<<<dim3(8, B_ * NG), 256>>>(x);
    gn_apply_kernel<<<dim3(8, NG, B_), 256>>>(x, gamma, beta);
    qkv_kernel<<<dim3(8, 3 * B_), 256, G2_SMEM>>>(bq, bk, bv);
    score_softmax_kernel<<<dim3(32, B_), 512, FS_SMEM>>>();
    pv_kernel<<<dim3(4, 2, B_), 256, G2_SMEM>>>(x, out);
}

// round 7
// speedup vs baseline: 1.0374x; 1.0374x over previous
#include <cuda_runtime.h>
#include <cuda_fp16.h>
#include <cstdint>

#define B_  16
#define C_  256
#define N_  1024
#define NG  4
#define GC  64

typedef __half fp16;

// ---- scratch (static device globals) ----
__device__ fp16  g_hT[(size_t)B_ * N_ * C_];   // groupnorm out, [b][n][c]
__device__ fp16  g_q [(size_t)B_ * N_ * C_];   // [b][n][d], pre-scaled by 1/16
__device__ fp16  g_k [(size_t)B_ * N_ * C_];
__device__ fp16  g_vt[(size_t)B_ * C_ * N_];   // V transposed: [b][d][m]
__device__ fp16  g_p [(size_t)B_ * N_ * N_];   // probs fp16 [query][key]
__device__ fp16  g_wq[C_ * C_];
__device__ fp16  g_wk[C_ * C_];
__device__ fp16  g_wv[C_ * C_];
__device__ float g_red[B_ * NG][8][2];         // groupnorm partial sums

// ---------------------------------------------------------------------------
// helpers (family-safe PTX: ldmatrix / mma.sync / cp.async)
// ---------------------------------------------------------------------------
__device__ __forceinline__ uint32_t smem_u32(const void* p) {
    return (uint32_t)__cvta_generic_to_shared(p);
}
__device__ __forceinline__ void ldsm4(uint32_t* r, uint32_t addr) {
    asm volatile("ldmatrix.sync.aligned.m8n8.x4.shared.b16 {%0,%1,%2,%3}, [%4];"
                 : "=r"(r[0]), "=r"(r[1]), "=r"(r[2]), "=r"(r[3]) : "r"(addr));
}
// f16 x f16 -> f16 accumulate: 2-reg accumulator (half the RF traffic of f32 acc)
__device__ __forceinline__ void mma16816h(uint32_t* c, const uint32_t* a, const uint32_t* b) {
    asm volatile(
        "mma.sync.aligned.m16n8k16.row.col.f16.f16.f16.f16 "
        "{%0,%1}, {%2,%3,%4,%5}, {%6,%7}, {%0,%1};"
        : "+r"(c[0]), "+r"(c[1])
        : "r"(a[0]), "r"(a[1]), "r"(a[2]), "r"(a[3]), "r"(b[0]), "r"(b[1]));
}
__device__ __forceinline__ void cp16(uint32_t dst, const void* src) {
    asm volatile("cp.async.cg.shared.global [%0], [%1], 16;" :: "r"(dst), "l"(src));
}
__device__ __forceinline__ void cp_commit() { asm volatile("cp.async.commit_group;" ::: "memory"); }
__device__ __forceinline__ void cp_wait0()  { asm volatile("cp.async.wait_group 0;" ::: "memory"); }
__device__ __forceinline__ void cp_wait2()  { asm volatile("cp.async.wait_group 2;" ::: "memory"); }

__device__ __forceinline__ float2 h2f2(uint32_t u) {
    return __half22float2(*reinterpret_cast<__half2*>(&u));
}
__device__ __forceinline__ uint32_t f2h2(float a, float b) {
    __half2 h = __floats2half2_rn(a, b);
    return *reinterpret_cast<uint32_t*>(&h);
}

#define KT      32
#define STRIDE  40
#define TILE_B  (128 * STRIDE * 2)      // 10240 B per operand tile
#define STG_B   (2 * TILE_B)            // 20480 B per stage (A+B)
#define NSTAGE  4
#define GEMM_SMEM (NSTAGE * STG_B)      // 81920 B

// ---------------------------------------------------------------------------
// Multistage 128x128 GEMM: acc += A[128,K] * B[128,K]^T (fp16 -> fp16 acc)
// 256 threads, warp grid 4(m) x 2(n), 4-stage cp.async pipeline.
// acc[2][8][2] packed half2: [0] = rows r, cols (c,c+1); [1] = rows r+8.
// ---------------------------------------------------------------------------
__device__ __forceinline__ void copy_tile(const fp16* A, int lda, const fp16* B, int ldb,
                                          uint32_t sA, uint32_t sB, int k0, int tid) {
    #pragma unroll
    for (int c = 0; c < 2; c++) {
        int id = tid + 256 * c;
        int row = id >> 2, col = (id & 3) * 8;
        uint32_t off = (uint32_t)(row * STRIDE + col) * 2;
        cp16(sA + off, A + (size_t)row * lda + k0 + col);
        cp16(sB + off, B + (size_t)row * ldb + k0 + col);
    }
    cp_commit();
}

__device__ __forceinline__ void gemm_ms(const fp16* A, int lda, const fp16* B, int ldb,
                                        int T, char* smem, uint32_t acc[2][8][2], int tid) {
    int lane = tid & 31, wid = tid >> 5;
    int wm = wid & 3, wn = wid >> 2;
    uint32_t base = smem_u32(smem);

    #pragma unroll
    for (int s = 0; s < NSTAGE - 1; s++)
        copy_tile(A, lda, B, ldb, base + s * STG_B, base + s * STG_B + TILE_B, s * KT, tid);

    int ar = lane & 15, ak = (lane >> 4) * 8;
    for (int t = 0; t < T; t++) {
        cp_wait2();
        __syncthreads();
        int nxt = t + NSTAGE - 1;
        if (nxt < T) {
            uint32_t sb = base + (nxt % NSTAGE) * STG_B;
            copy_tile(A, lda, B, ldb, sb, sb + TILE_B, nxt * KT, tid);
        } else {
            cp_commit();
        }
        uint32_t aB = base + (t % NSTAGE) * STG_B;
        uint32_t bB = aB + TILE_B;

        #pragma unroll
        for (int kk = 0; kk < 2; kk++) {
            uint32_t af[2][4];
            #pragma unroll
            for (int mt = 0; mt < 2; mt++)
                ldsm4(af[mt], aB + (uint32_t)((wm * 32 + mt * 16 + ar) * STRIDE + kk * 16 + ak) * 2);
            #pragma unroll
            for (int np = 0; np < 4; np++) {
                uint32_t r[4];
                ldsm4(r, bB + (uint32_t)((wn * 64 + np * 16 + ar) * STRIDE + kk * 16 + ak) * 2);
                uint32_t b0[2] = {r[0], r[2]};
                uint32_t b1[2] = {r[1], r[3]};
                #pragma unroll
                for (int mt = 0; mt < 2; mt++) {
                    mma16816h(acc[mt][np * 2],     af[mt], b0);
                    mma16816h(acc[mt][np * 2 + 1], af[mt], b1);
                }
            }
        }
    }
}

// ---------------------------------------------------------------------------
// 0. weights fp32 -> fp16
// ---------------------------------------------------------------------------
__global__ __launch_bounds__(256) void prep_kernel(const float* __restrict__ Wq,
                                                   const float* __restrict__ Wk,
                                                   const float* __restrict__ Wv) {
    int i = blockIdx.x * 256 + threadIdx.x;
    float4 a; uint2 u;
    a = reinterpret_cast<const float4*>(Wq)[i];
    u.x = f2h2(a.x, a.y); u.y = f2h2(a.z, a.w);
    reinterpret_cast<uint2*>(g_wq)[i] = u;
    a = reinterpret_cast<const float4*>(Wk)[i];
    u.x = f2h2(a.x, a.y); u.y = f2h2(a.z, a.w);
    reinterpret_cast<uint2*>(g_wk)[i] = u;
    a = reinterpret_cast<const float4*>(Wv)[i];
    u.x = f2h2(a.x, a.y); u.y = f2h2(a.z, a.w);
    reinterpret_cast<uint2*>(g_wv)[i] = u;
}

// ---------------------------------------------------------------------------
// 1a. GroupNorm stats
// ---------------------------------------------------------------------------
__global__ __launch_bounds__(256) void gn_stats_kernel(const float* __restrict__ x) {
    int s = blockIdx.x, bg = blockIdx.y;
    const float* xp = x + (size_t)bg * GC * N_ + (size_t)s * 8192;
    float sum = 0.f, ss = 0.f;
    #pragma unroll
    for (int i = 0; i < 8; i++) {
        float4 v = reinterpret_cast<const float4*>(xp)[threadIdx.x + i * 256];
        sum += v.x + v.y + v.z + v.w;
        ss  += v.x * v.x + v.y * v.y + v.z * v.z + v.w * v.w;
    }
    __shared__ float sh1[256], sh2[256];
    sh1[threadIdx.x] = sum; sh2[threadIdx.x] = ss;
    __syncthreads();
    for (int o = 128; o > 0; o >>= 1) {
        if (threadIdx.x < o) {
            sh1[threadIdx.x] += sh1[threadIdx.x + o];
            sh2[threadIdx.x] += sh2[threadIdx.x + o];
        }
        __syncthreads();
    }
    if (threadIdx.x == 0) {
        g_red[bg][s][0] = sh1[0];
        g_red[bg][s][1] = sh2[0];
    }
}

// ---------------------------------------------------------------------------
// 1b. GroupNorm apply + transpose: x[b][c][n] -> hT[b][n][c] fp16
// ---------------------------------------------------------------------------
__global__ __launch_bounds__(256) void gn_apply_kernel(const float* __restrict__ x,
                                                       const float* __restrict__ gamma,
                                                       const float* __restrict__ beta) {
    int ns = blockIdx.x, g = blockIdx.y, b = blockIdx.z;
    int bg = b * NG + g;
    float sum = 0.f, ss = 0.f;
    #pragma unroll
    for (int i = 0; i < 8; i++) { sum += g_red[bg][i][0]; ss += g_red[bg][i][1]; }
    const float inv_n = 1.0f / (GC * N_);
    float mean = sum * inv_n;
    float var  = ss * inv_n - mean * mean;
    float rstd = rsqrtf(var + 1e-5f);

    const float* xp = x + (size_t)bg * GC * N_;
    fp16* out = g_hT + (size_t)b * N_ * C_ + g * GC;
    __shared__ float tile[32 * 65];
    int tid = threadIdx.x;
    int nbase = ns * 128;
    for (int n0 = nbase; n0 < nbase + 128; n0 += 32) {
        for (int e = tid; e < GC * 32; e += 256) {
            int c = e >> 5, n = e & 31;
            float v = (xp[(size_t)c * N_ + n0 + n] - mean) * rstd;
            v = v * __ldg(&gamma[g * GC + c]) + __ldg(&beta[g * GC + c]);
            tile[n * 65 + c] = v;
        }
        __syncthreads();
        {
            int n = tid >> 3, u = tid & 7;
            uint32_t pk[4];
            #pragma unroll
            for (int j = 0; j < 4; j++)
                pk[j] = f2h2(tile[n * 65 + u * 8 + 2 * j], tile[n * 65 + u * 8 + 2 * j + 1]);
            *reinterpret_cast<uint4*>(out + (size_t)(n0 + n) * C_ + u * 8) =
                *reinterpret_cast<uint4*>(pk);
        }
        __syncthreads();
    }
}

// ---------------------------------------------------------------------------
// 2. QKV: out = hT @ W^T + b.  mi=0 -> q (x 1/16), mi=1 -> k, mi=2 -> Vt.
// ---------------------------------------------------------------------------
__global__ __launch_bounds__(256) void qkv_kernel(const float* __restrict__ bq,
                                                  const float* __restrict__ bk,
                                                  const float* __restrict__ bv) {
    extern __shared__ __align__(16) char dsm[];
    int tid = threadIdx.x;
    int mi = blockIdx.z % 3, b = blockIdx.z / 3;
    int n0 = blockIdx.x * 128, m0 = blockIdx.y * 128;
    const fp16* A  = g_hT + (size_t)b * N_ * C_ + (size_t)m0 * C_;
    const fp16* Bm = (mi == 0 ? g_wq : mi == 1 ? g_wk : g_wv) + (size_t)n0 * C_;
    uint32_t acc[2][8][2] = {};
    gemm_ms(A, C_, Bm, C_, C_ / KT, dsm, acc, tid);

    int lane = tid & 31, wid = tid >> 5;
    int wm = wid & 3, wn = wid >> 2;
    int quad = lane >> 2, qt = lane & 3;
    const float* bias = (mi == 0) ? bq : (mi == 1) ? bk : bv;

    if (mi < 2) {
        fp16* out = ((mi == 0) ? g_q : g_k) + (size_t)b * N_ * C_;
        float scale = (mi == 0) ? 0.0625f : 1.0f;
        #pragma unroll
        for (int mt = 0; mt < 2; mt++) {
            int r0 = m0 + wm * 32 + mt * 16 + quad;
            #pragma unroll
            for (int nt = 0; nt < 8; nt++) {
                int d = n0 + wn * 64 + nt * 8 + qt * 2;
                float b0 = __ldg(&bias[d]), b1 = __ldg(&bias[d + 1]);
                float2 c01 = h2f2(acc[mt][nt][0]);
                float2 c23 = h2f2(acc[mt][nt][1]);
                uint32_t h0 = f2h2((c01.x + b0) * scale, (c01.y + b1) * scale);
                uint32_t h1 = f2h2((c23.x + b0) * scale, (c23.y + b1) * scale);
                *reinterpret_cast<uint32_t*>(out + (size_t)r0 * C_ + d) = h0;
                *reinterpret_cast<uint32_t*>(out + (size_t)(r0 + 8) * C_ + d) = h1;
            }
        }
    } else {
        fp16* st = reinterpret_cast<fp16*>(dsm);   // [256 d][stride 136]
        __syncthreads();
        #pragma unroll
        for (int mt = 0; mt < 2; mt++) {
            int ml = wm * 32 + mt * 16 + quad;
            #pragma unroll
            for (int nt = 0; nt < 8; nt++) {
                int dl = wn * 64 + nt * 8 + qt * 2;
                float b0 = __ldg(&bias[n0 + dl]), b1 = __ldg(&bias[n0 + dl + 1]);
                float2 c01 = h2f2(acc[mt][nt][0]);
                float2 c23 = h2f2(acc[mt][nt][1]);
                st[dl * 136 + ml]           = __float2half_rn(c01.x + b0);
                st[(dl + 1) * 136 + ml]     = __float2half_rn(c01.y + b1);
                st[dl * 136 + ml + 8]       = __float2half_rn(c23.x + b0);
                st[(dl + 1) * 136 + ml + 8] = __float2half_rn(c23.y + b1);
            }
        }
        __syncthreads();
        fp16* outv = g_vt + (size_t)b * C_ * N_;
        #pragma unroll
        for (int c = 0; c < 8; c++) {
            int id = tid + 256 * c;
            int d = id >> 4, ch = (id & 15) * 8;
            *reinterpret_cast<uint4*>(outv + (size_t)(n0 + d) * N_ + m0 + ch) =
                *reinterpret_cast<uint4*>(st + d * 136 + ch);
        }
    }
}

// ---------------------------------------------------------------------------
// 3. FUSED scores+softmax, 512 threads: warp grid 2(q) x 8(keys).
// ---------------------------------------------------------------------------
#define FS_STAGE ((1024 + 32) * STRIDE * 2)
#define FS_SMEM  (2 * FS_STAGE)

__device__ __forceinline__ void fs_copy(const fp16* Q, const fp16* K,
                                        uint32_t sK, uint32_t sQ, int k0, int tid) {
    #pragma unroll
    for (int i = 0; i < 9; i++) {
        int id = tid + 512 * i;
        if (id < 4096) {
            int row = id >> 2, col = (id & 3) * 8;
            cp16(sK + (uint32_t)(row * STRIDE + col) * 2, K + (size_t)row * C_ + k0 + col);
        } else if (id < 4224) {
            int q = id - 4096;
            int row = q >> 2, col = (q & 3) * 8;
            cp16(sQ + (uint32_t)(row * STRIDE + col) * 2, Q + (size_t)row * C_ + k0 + col);
        }
    }
    cp_commit();
}

__global__ __launch_bounds__(512, 1) void score_softmax_kernel() {
    extern __shared__ __align__(16) char dsm[];
    int tid = threadIdx.x;
    int lane = tid & 31, wid = tid >> 5;
    int quad = lane >> 2, qt = lane & 3;
    int wn = wid & 7, wq = wid >> 3;
    int b = blockIdx.y, m0 = blockIdx.x * 32;

    const fp16* Q = g_q + ((size_t)b * N_ + m0) * C_;
    const fp16* K = g_k + (size_t)b * N_ * C_;

    uint32_t base = smem_u32(dsm);
    uint32_t sK0 = base, sQ0 = base + 1024 * STRIDE * 2;
    uint32_t sK1 = base + FS_STAGE, sQ1 = sK1 + 1024 * STRIDE * 2;

    uint32_t acc[16][2] = {};   // packed half2; [0]=rows r cols(c,c+1), [1]=rows r+8

    fs_copy(Q, K, sK0, sQ0, 0, tid);
    int ar = lane & 15, ak = (lane >> 4) * 8;
    const int T = C_ / KT;  // 8
    for (int t = 0; t < T; t++) {
        cp_wait0();
        __syncthreads();
        if (t + 1 < T)
            fs_copy(Q, K, (t & 1) ? sK0 : sK1, (t & 1) ? sQ0 : sQ1, (t + 1) * KT, tid);
        else
            cp_commit();
        uint32_t kB = (t & 1) ? sK1 : sK0;
        uint32_t qB = (t & 1) ? sQ1 : sQ0;

        #pragma unroll
        for (int kk = 0; kk < 2; kk++) {
            uint32_t af[4];
            ldsm4(af, qB + (uint32_t)((wq * 16 + ar) * STRIDE + kk * 16 + ak) * 2);
            #pragma unroll
            for (int np = 0; np < 8; np++) {
                uint32_t r[4];
                ldsm4(r, kB + (uint32_t)((wn * 128 + np * 16 + ar) * STRIDE + kk * 16 + ak) * 2);
                uint32_t b0[2] = {r[0], r[2]};
                uint32_t b1[2] = {r[1], r[3]};
                mma16816h(acc[np * 2],     af, b0);
                mma16816h(acc[np * 2 + 1], af, b1);
            }
        }
    }

    // ---- softmax over rows (keys distributed over 8 wn warps) ----
    float* red  = reinterpret_cast<float*>(dsm);
    float* red2 = red + 32 * 8;

    float rmax[2] = {-1e30f, -1e30f};
    #pragma unroll
    for (int nt = 0; nt < 16; nt++) {
        float2 a01 = h2f2(acc[nt][0]), a23 = h2f2(acc[nt][1]);
        rmax[0] = fmaxf(rmax[0], fmaxf(a01.x, a01.y));
        rmax[1] = fmaxf(rmax[1], fmaxf(a23.x, a23.y));
    }
    #pragma unroll
    for (int h = 0; h < 2; h++) {
        rmax[h] = fmaxf(rmax[h], __shfl_xor_sync(0xffffffffu, rmax[h], 1));
        rmax[h] = fmaxf(rmax[h], __shfl_xor_sync(0xffffffffu, rmax[h], 2));
    }
    if (qt == 0) {
        red[(wq * 16 + quad) * 8 + wn]     = rmax[0];
        red[(wq * 16 + 8 + quad) * 8 + wn] = rmax[1];
    }
    __syncthreads();
    float M[2];
    #pragma unroll
    for (int h = 0; h < 2; h++) {
        float m = -1e30f;
        #pragma unroll
        for (int w8 = 0; w8 < 8; w8++) m = fmaxf(m, red[(wq * 16 + h * 8 + quad) * 8 + w8]);
        M[h] = m;
    }

    float rsum[2] = {0.f, 0.f};
    #pragma unroll
    for (int nt = 0; nt < 16; nt++) {
        float2 a01 = h2f2(acc[nt][0]), a23 = h2f2(acc[nt][1]);
        float e0 = __expf(a01.x - M[0]), e1 = __expf(a01.y - M[0]);
        float e2 = __expf(a23.x - M[1]), e3 = __expf(a23.y - M[1]);
        rsum[0] += e0 + e1;
        rsum[1] += e2 + e3;
        acc[nt][0] = f2h2(e0, e1);        // stash exp() packed (P is fp16 anyway)
        acc[nt][1] = f2h2(e2, e3);
    }
    #pragma unroll
    for (int h = 0; h < 2; h++) {
        rsum[h] += __shfl_xor_sync(0xffffffffu, rsum[h], 1);
        rsum[h] += __shfl_xor_sync(0xffffffffu, rsum[h], 2);
    }
    if (qt == 0) {
        red2[(wq * 16 + quad) * 8 + wn]     = rsum[0];
        red2[(wq * 16 + 8 + quad) * 8 + wn] = rsum[1];
    }
    __syncthreads();
    float inv[2];
    #pragma unroll
    for (int h = 0; h < 2; h++) {
        float s = 0.f;
        #pragma unroll
        for (int w8 = 0; w8 < 8; w8++) s += red2[(wq * 16 + h * 8 + quad) * 8 + w8];
        inv[h] = 1.0f / s;
    }

    fp16* P = g_p + (size_t)b * N_ * N_;
    int r0 = m0 + wq * 16 + quad;
    #pragma unroll
    for (int nt = 0; nt < 16; nt++) {
        int cc = wn * 128 + nt * 8 + qt * 2;
        float2 e01 = h2f2(acc[nt][0]), e23 = h2f2(acc[nt][1]);
        *reinterpret_cast<uint32_t*>(P + (size_t)r0 * N_ + cc) =
            f2h2(e01.x * inv[0], e01.y * inv[0]);
        *reinterpret_cast<uint32_t*>(P + (size_t)(r0 + 8) * N_ + cc) =
            f2h2(e23.x * inv[1], e23.y * inv[1]);
    }
}

// ---------------------------------------------------------------------------
// 5. PV as O^T: out[b][c][n] = sum_m Vt[b][c][m] * P[b][n][m] + x[b][c][n]
// ---------------------------------------------------------------------------
__global__ __launch_bounds__(256) void pv_kernel(const float* __restrict__ x,
                                                 float* __restrict__ outp) {
    extern __shared__ __align__(16) char dsm[];
    int tid = threadIdx.x;
    int b = blockIdx.z;
    int n0 = blockIdx.x * 128;   // token tile
    int m0 = blockIdx.y * 128;   // channel tile
    const fp16* A  = g_vt + (size_t)b * C_ * N_ + (size_t)m0 * N_;
    const fp16* Bm = g_p  + (size_t)b * N_ * N_ + (size_t)n0 * N_;
    uint32_t acc[2][8][2] = {};
    gemm_ms(A, N_, Bm, N_, N_ / KT, dsm, acc, tid);

    int lane = tid & 31, wid = tid >> 5;
    int wm = wid & 3, wn = wid >> 2;
    int quad = lane >> 2, qt = lane & 3;
    #pragma unroll
    for (int mt = 0; mt < 2; mt++) {
        int cg = m0 + wm * 32 + mt * 16 + quad;
        #pragma unroll
        for (int nt = 0; nt < 8; nt++) {
            int ng = n0 + wn * 64 + nt * 8 + qt * 2;
            size_t base = ((size_t)b * C_ + cg) * N_ + ng;
            float2 c01 = h2f2(acc[mt][nt][0]);
            float2 c23 = h2f2(acc[mt][nt][1]);
            float2 xv = *reinterpret_cast<const float2*>(x + base);
            *reinterpret_cast<float2*>(outp + base) =
                make_float2(c01.x + xv.x, c01.y + xv.y);
            size_t base8 = base + (size_t)8 * N_;
            float2 xv8 = *reinterpret_cast<const float2*>(x + base8);
            *reinterpret_cast<float2*>(outp + base8) =
                make_float2(c23.x + xv8.x, c23.y + xv8.y);
        }
    }
}

// ---------------------------------------------------------------------------
extern "C" void kernel_launch(void* const* d_in, const int* in_sizes, int n_in,
                              void* d_out, int out_size) {
    const float* x     = (const float*)d_in[0];
    const float* Wq    = (const float*)d_in[1];
    const float* bq    = (const float*)d_in[2];
    const float* Wk    = (const float*)d_in[3];
    const float* bk    = (const float*)d_in[4];
    const float* Wv    = (const float*)d_in[5];
    const float* bv    = (const float*)d_in[6];
    const float* gamma = (const float*)d_in[7];
    const float* beta  = (const float*)d_in[8];
    float* out = (float*)d_out;

    cudaFuncSetAttribute(qkv_kernel, cudaFuncAttributeMaxDynamicSharedMemorySize, GEMM_SMEM);
    cudaFuncSetAttribute(pv_kernel, cudaFuncAttributeMaxDynamicSharedMemorySize, GEMM_SMEM);
    cudaFuncSetAttribute(score_softmax_kernel, cudaFuncAttributeMaxDynamicSharedMemorySize, FS_SMEM);

    prep_kernel<<<64, 256>>>(Wq, Wk, Wv);
    gn_stats_kernel<<<dim3(8, B_ * NG), 256>>>(x);
    gn_apply_kernel<<<dim3(8, NG, B_), 256>>>(x, gamma, beta);
    qkv_kernel<<<dim3(2, 8, 3 * B_), 256, GEMM_SMEM>>>(bq, bk, bv);
    score_softmax_kernel<<<dim3(32, B_), 512, FS_SMEM>>>();
    pv_kernel<<<dim3(8, 2, B_), 256, GEMM_SMEM>>>(x, out);
}

// round 8
// speedup vs baseline: 1.1264x; 1.0858x over previous
#include <cuda_runtime.h>
#include <cuda_fp16.h>
#include <cstdint>

#define B_  16
#define C_  256
#define N_  1024
#define NG  4
#define GC  64

typedef __half fp16;

// ---- scratch (static device globals) ----
__device__ fp16  g_hT[(size_t)B_ * N_ * C_];   // groupnorm out, [b][n][c]
__device__ fp16  g_q [(size_t)B_ * N_ * C_];   // [b][n][d], pre-scaled by 1/16
__device__ fp16  g_k [(size_t)B_ * N_ * C_];
__device__ fp16  g_vt[(size_t)B_ * C_ * N_];   // V transposed: [b][d][m]
__device__ fp16  g_p [(size_t)B_ * N_ * N_];   // probs fp16 [query][key]
__device__ fp16  g_wq[C_ * C_];
__device__ fp16  g_wk[C_ * C_];
__device__ fp16  g_wv[C_ * C_];
__device__ float g_red[B_ * NG][8][2];         // groupnorm partial sums

// ---------------------------------------------------------------------------
// helpers (family-safe PTX: ldmatrix / mma.sync / cp.async)
// ---------------------------------------------------------------------------
__device__ __forceinline__ uint32_t smem_u32(const void* p) {
    return (uint32_t)__cvta_generic_to_shared(p);
}
__device__ __forceinline__ void ldsm4(uint32_t* r, uint32_t addr) {
    asm volatile("ldmatrix.sync.aligned.m8n8.x4.shared.b16 {%0,%1,%2,%3}, [%4];"
                 : "=r"(r[0]), "=r"(r[1]), "=r"(r[2]), "=r"(r[3]) : "r"(addr));
}
__device__ __forceinline__ void mma16816h(uint32_t* c, const uint32_t* a, const uint32_t* b) {
    asm volatile(
        "mma.sync.aligned.m16n8k16.row.col.f16.f16.f16.f16 "
        "{%0,%1}, {%2,%3,%4,%5}, {%6,%7}, {%0,%1};"
        : "+r"(c[0]), "+r"(c[1])
        : "r"(a[0]), "r"(a[1]), "r"(a[2]), "r"(a[3]), "r"(b[0]), "r"(b[1]));
}
__device__ __forceinline__ void cp16(uint32_t dst, const void* src) {
    asm volatile("cp.async.cg.shared.global [%0], [%1], 16;" :: "r"(dst), "l"(src));
}
__device__ __forceinline__ void cp_commit() { asm volatile("cp.async.commit_group;" ::: "memory"); }
__device__ __forceinline__ void cp_wait0()  { asm volatile("cp.async.wait_group 0;" ::: "memory"); }
__device__ __forceinline__ void cp_wait1()  { asm volatile("cp.async.wait_group 1;" ::: "memory"); }

__device__ __forceinline__ float2 h2f2(uint32_t u) {
    return __half22float2(*reinterpret_cast<__half2*>(&u));
}
__device__ __forceinline__ uint32_t f2h2(float a, float b) {
    __half2 h = __floats2half2_rn(a, b);
    return *reinterpret_cast<uint32_t*>(&h);
}

#define KT      32
#define STRIDE  40
#define TILE_B  (128 * STRIDE * 2)      // 10240 B per operand tile
#define STG_B   (2 * TILE_B)            // 20480 B per stage (A+B)
#define NSTAGE  3
#define GEMM_SMEM (NSTAGE * STG_B)      // 61440 B -> 3 CTAs/SM

// ---------------------------------------------------------------------------
// Multistage 128x128 GEMM: acc += A[128,K] * B[128,K]^T (fp16 -> fp16 acc)
// 256 threads, warp grid 4(m) x 2(n), 3-stage cp.async pipeline.
// ---------------------------------------------------------------------------
__device__ __forceinline__ void copy_tile(const fp16* A, int lda, const fp16* B, int ldb,
                                          uint32_t sA, uint32_t sB, int k0, int tid) {
    #pragma unroll
    for (int c = 0; c < 2; c++) {
        int id = tid + 256 * c;
        int row = id >> 2, col = (id & 3) * 8;
        uint32_t off = (uint32_t)(row * STRIDE + col) * 2;
        cp16(sA + off, A + (size_t)row * lda + k0 + col);
        cp16(sB + off, B + (size_t)row * ldb + k0 + col);
    }
    cp_commit();
}

__device__ __forceinline__ void gemm_ms(const fp16* A, int lda, const fp16* B, int ldb,
                                        int T, char* smem, uint32_t acc[2][8][2], int tid) {
    int lane = tid & 31, wid = tid >> 5;
    int wm = wid & 3, wn = wid >> 2;
    uint32_t base = smem_u32(smem);

    #pragma unroll
    for (int s = 0; s < NSTAGE - 1; s++)
        copy_tile(A, lda, B, ldb, base + s * STG_B, base + s * STG_B + TILE_B, s * KT, tid);

    int ar = lane & 15, ak = (lane >> 4) * 8;
    for (int t = 0; t < T; t++) {
        cp_wait1();              // tile t resident (allow 1 younger pending)
        __syncthreads();
        int nxt = t + NSTAGE - 1;
        if (nxt < T) {
            uint32_t sb = base + (nxt % NSTAGE) * STG_B;
            copy_tile(A, lda, B, ldb, sb, sb + TILE_B, nxt * KT, tid);
        } else {
            cp_commit();
        }
        uint32_t aB = base + (t % NSTAGE) * STG_B;
        uint32_t bB = aB + TILE_B;

        #pragma unroll
        for (int kk = 0; kk < 2; kk++) {
            uint32_t af[2][4];
            #pragma unroll
            for (int mt = 0; mt < 2; mt++)
                ldsm4(af[mt], aB + (uint32_t)((wm * 32 + mt * 16 + ar) * STRIDE + kk * 16 + ak) * 2);
            #pragma unroll
            for (int np = 0; np < 4; np++) {
                uint32_t r[4];
                ldsm4(r, bB + (uint32_t)((wn * 64 + np * 16 + ar) * STRIDE + kk * 16 + ak) * 2);
                uint32_t b0[2] = {r[0], r[2]};
                uint32_t b1[2] = {r[1], r[3]};
                #pragma unroll
                for (int mt = 0; mt < 2; mt++) {
                    mma16816h(acc[mt][np * 2],     af[mt], b0);
                    mma16816h(acc[mt][np * 2 + 1], af[mt], b1);
                }
            }
        }
    }
}

// ---------------------------------------------------------------------------
// 1a. GroupNorm stats (blocks 0..511) + weight fp32->fp16 conversion (512..575)
// ---------------------------------------------------------------------------
__global__ __launch_bounds__(256) void gn_stats_kernel(const float* __restrict__ x,
                                                       const float* __restrict__ Wq,
                                                       const float* __restrict__ Wk,
                                                       const float* __restrict__ Wv) {
    int bx = blockIdx.x;
    if (bx >= 512) {
        int i = (bx - 512) * 256 + threadIdx.x;
        float4 a; uint2 u;
        a = reinterpret_cast<const float4*>(Wq)[i];
        u.x = f2h2(a.x, a.y); u.y = f2h2(a.z, a.w);
        reinterpret_cast<uint2*>(g_wq)[i] = u;
        a = reinterpret_cast<const float4*>(Wk)[i];
        u.x = f2h2(a.x, a.y); u.y = f2h2(a.z, a.w);
        reinterpret_cast<uint2*>(g_wk)[i] = u;
        a = reinterpret_cast<const float4*>(Wv)[i];
        u.x = f2h2(a.x, a.y); u.y = f2h2(a.z, a.w);
        reinterpret_cast<uint2*>(g_wv)[i] = u;
        return;
    }
    int s = bx & 7, bg = bx >> 3;
    const float* xp = x + (size_t)bg * GC * N_ + (size_t)s * 8192;
    float sum = 0.f, ss = 0.f;
    #pragma unroll
    for (int i = 0; i < 8; i++) {
        float4 v = reinterpret_cast<const float4*>(xp)[threadIdx.x + i * 256];
        sum += v.x + v.y + v.z + v.w;
        ss  += v.x * v.x + v.y * v.y + v.z * v.z + v.w * v.w;
    }
    __shared__ float sh1[256], sh2[256];
    sh1[threadIdx.x] = sum; sh2[threadIdx.x] = ss;
    __syncthreads();
    for (int o = 128; o > 0; o >>= 1) {
        if (threadIdx.x < o) {
            sh1[threadIdx.x] += sh1[threadIdx.x + o];
            sh2[threadIdx.x] += sh2[threadIdx.x + o];
        }
        __syncthreads();
    }
    if (threadIdx.x == 0) {
        g_red[bg][s][0] = sh1[0];
        g_red[bg][s][1] = sh2[0];
    }
}

// ---------------------------------------------------------------------------
// 1b. GroupNorm apply + transpose: x[b][c][n] -> hT[b][n][c] fp16
// ---------------------------------------------------------------------------
__global__ __launch_bounds__(256) void gn_apply_kernel(const float* __restrict__ x,
                                                       const float* __restrict__ gamma,
                                                       const float* __restrict__ beta) {
    int ns = blockIdx.x, g = blockIdx.y, b = blockIdx.z;
    int bg = b * NG + g;
    float sum = 0.f, ss = 0.f;
    #pragma unroll
    for (int i = 0; i < 8; i++) { sum += g_red[bg][i][0]; ss += g_red[bg][i][1]; }
    const float inv_n = 1.0f / (GC * N_);
    float mean = sum * inv_n;
    float var  = ss * inv_n - mean * mean;
    float rstd = rsqrtf(var + 1e-5f);

    const float* xp = x + (size_t)bg * GC * N_;
    fp16* out = g_hT + (size_t)b * N_ * C_ + g * GC;
    __shared__ float tile[32 * 65];
    int tid = threadIdx.x;
    int nbase = ns * 128;
    for (int n0 = nbase; n0 < nbase + 128; n0 += 32) {
        for (int e = tid; e < GC * 32; e += 256) {
            int c = e >> 5, n = e & 31;
            float v = (xp[(size_t)c * N_ + n0 + n] - mean) * rstd;
            v = v * __ldg(&gamma[g * GC + c]) + __ldg(&beta[g * GC + c]);
            tile[n * 65 + c] = v;
        }
        __syncthreads();
        {
            int n = tid >> 3, u = tid & 7;
            uint32_t pk[4];
            #pragma unroll
            for (int j = 0; j < 4; j++)
                pk[j] = f2h2(tile[n * 65 + u * 8 + 2 * j], tile[n * 65 + u * 8 + 2 * j + 1]);
            *reinterpret_cast<uint4*>(out + (size_t)(n0 + n) * C_ + u * 8) =
                *reinterpret_cast<uint4*>(pk);
        }
        __syncthreads();
    }
}

// ---------------------------------------------------------------------------
// 2. QKV: out = hT @ W^T + b.  mi=0 -> q (x 1/16), mi=1 -> k, mi=2 -> Vt.
// ---------------------------------------------------------------------------
__global__ __launch_bounds__(256) void qkv_kernel(const float* __restrict__ bq,
                                                  const float* __restrict__ bk,
                                                  const float* __restrict__ bv) {
    extern __shared__ __align__(16) char dsm[];
    int tid = threadIdx.x;
    int mi = blockIdx.z % 3, b = blockIdx.z / 3;
    int n0 = blockIdx.x * 128, m0 = blockIdx.y * 128;
    const fp16* A  = g_hT + (size_t)b * N_ * C_ + (size_t)m0 * C_;
    const fp16* Bm = (mi == 0 ? g_wq : mi == 1 ? g_wk : g_wv) + (size_t)n0 * C_;
    uint32_t acc[2][8][2] = {};
    gemm_ms(A, C_, Bm, C_, C_ / KT, dsm, acc, tid);

    int lane = tid & 31, wid = tid >> 5;
    int wm = wid & 3, wn = wid >> 2;
    int quad = lane >> 2, qt = lane & 3;
    const float* bias = (mi == 0) ? bq : (mi == 1) ? bk : bv;

    if (mi < 2) {
        fp16* out = ((mi == 0) ? g_q : g_k) + (size_t)b * N_ * C_;
        float scale = (mi == 0) ? 0.0625f : 1.0f;
        #pragma unroll
        for (int mt = 0; mt < 2; mt++) {
            int r0 = m0 + wm * 32 + mt * 16 + quad;
            #pragma unroll
            for (int nt = 0; nt < 8; nt++) {
                int d = n0 + wn * 64 + nt * 8 + qt * 2;
                float b0 = __ldg(&bias[d]), b1 = __ldg(&bias[d + 1]);
                float2 c01 = h2f2(acc[mt][nt][0]);
                float2 c23 = h2f2(acc[mt][nt][1]);
                uint32_t h0 = f2h2((c01.x + b0) * scale, (c01.y + b1) * scale);
                uint32_t h1 = f2h2((c23.x + b0) * scale, (c23.y + b1) * scale);
                *reinterpret_cast<uint32_t*>(out + (size_t)r0 * C_ + d) = h0;
                *reinterpret_cast<uint32_t*>(out + (size_t)(r0 + 8) * C_ + d) = h1;
            }
        }
    } else {
        fp16* st = reinterpret_cast<fp16*>(dsm);   // [256 d][stride 136]
        __syncthreads();
        #pragma unroll
        for (int mt = 0; mt < 2; mt++) {
            int ml = wm * 32 + mt * 16 + quad;
            #pragma unroll
            for (int nt = 0; nt < 8; nt++) {
                int dl = wn * 64 + nt * 8 + qt * 2;
                float b0 = __ldg(&bias[n0 + dl]), b1 = __ldg(&bias[n0 + dl + 1]);
                float2 c01 = h2f2(acc[mt][nt][0]);
                float2 c23 = h2f2(acc[mt][nt][1]);
                st[dl * 136 + ml]           = __float2half_rn(c01.x + b0);
                st[(dl + 1) * 136 + ml]     = __float2half_rn(c01.y + b1);
                st[dl * 136 + ml + 8]       = __float2half_rn(c23.x + b0);
                st[(dl + 1) * 136 + ml + 8] = __float2half_rn(c23.y + b1);
            }
        }
        __syncthreads();
        fp16* outv = g_vt + (size_t)b * C_ * N_;
        #pragma unroll
        for (int c = 0; c < 8; c++) {
            int id = tid + 256 * c;
            int d = id >> 4, ch = (id & 15) * 8;
            *reinterpret_cast<uint4*>(outv + (size_t)(n0 + d) * N_ + m0 + ch) =
                *reinterpret_cast<uint4*>(st + d * 136 + ch);
        }
    }
}

// ---------------------------------------------------------------------------
// 3. FUSED scores+softmax, 512 threads, 64 queries/CTA.
//    Warp grid: wq (2) x 32 query rows, wn (8) x 128-key slices.
// ---------------------------------------------------------------------------
#define FS_STAGE ((1024 + 64) * STRIDE * 2)   // 87040 B (K tile + 64-row Q tile)
#define FS_SMEM  (2 * FS_STAGE)               // 174080 B

__device__ __forceinline__ void fs_copy(const fp16* Q, const fp16* K,
                                        uint32_t sK, uint32_t sQ, int k0, int tid) {
    #pragma unroll
    for (int i = 0; i < 9; i++) {
        int id = tid + 512 * i;
        if (id < 4096) {
            int row = id >> 2, col = (id & 3) * 8;
            cp16(sK + (uint32_t)(row * STRIDE + col) * 2, K + (size_t)row * C_ + k0 + col);
        } else if (id < 4352) {
            int q = id - 4096;
            int row = q >> 2, col = (q & 3) * 8;
            cp16(sQ + (uint32_t)(row * STRIDE + col) * 2, Q + (size_t)row * C_ + k0 + col);
        }
    }
    cp_commit();
}

__global__ __launch_bounds__(512, 1) void score_softmax_kernel() {
    extern __shared__ __align__(16) char dsm[];
    int tid = threadIdx.x;
    int lane = tid & 31, wid = tid >> 5;
    int quad = lane >> 2, qt = lane & 3;
    int wn = wid & 7, wq = wid >> 3;      // key-slice warp, query-group warp
    int b = blockIdx.y, m0 = blockIdx.x * 64;

    const fp16* Q = g_q + ((size_t)b * N_ + m0) * C_;
    const fp16* K = g_k + (size_t)b * N_ * C_;

    uint32_t base = smem_u32(dsm);
    uint32_t sK0 = base, sQ0 = base + 1024 * STRIDE * 2;
    uint32_t sK1 = base + FS_STAGE, sQ1 = sK1 + 1024 * STRIDE * 2;

    uint32_t acc[2][16][2] = {};   // [mt: q 16-row half][nt][2 packed half2]

    fs_copy(Q, K, sK0, sQ0, 0, tid);
    int ar = lane & 15, ak = (lane >> 4) * 8;
    const int T = C_ / KT;  // 8
    for (int t = 0; t < T; t++) {
        cp_wait0();
        __syncthreads();
        if (t + 1 < T)
            fs_copy(Q, K, (t & 1) ? sK0 : sK1, (t & 1) ? sQ0 : sQ1, (t + 1) * KT, tid);
        else
            cp_commit();
        uint32_t kB = (t & 1) ? sK1 : sK0;
        uint32_t qB = (t & 1) ? sQ1 : sQ0;

        #pragma unroll
        for (int kk = 0; kk < 2; kk++) {
            uint32_t af[2][4];
            #pragma unroll
            for (int mt = 0; mt < 2; mt++)
                ldsm4(af[mt], qB + (uint32_t)((wq * 32 + mt * 16 + ar) * STRIDE + kk * 16 + ak) * 2);
            #pragma unroll
            for (int np = 0; np < 8; np++) {
                uint32_t r[4];
                ldsm4(r, kB + (uint32_t)((wn * 128 + np * 16 + ar) * STRIDE + kk * 16 + ak) * 2);
                uint32_t b0[2] = {r[0], r[2]};
                uint32_t b1[2] = {r[1], r[3]};
                #pragma unroll
                for (int mt = 0; mt < 2; mt++) {
                    mma16816h(acc[mt][np * 2],     af[mt], b0);
                    mma16816h(acc[mt][np * 2 + 1], af[mt], b1);
                }
            }
        }
    }

    // ---- softmax over rows (keys distributed over 8 wn warps) ----
    float* red  = reinterpret_cast<float*>(dsm);   // [64 rows][8 warps]
    float* red2 = red + 64 * 8;

    float rmax[2][2];
    #pragma unroll
    for (int mt = 0; mt < 2; mt++) {
        float m0v = -1e30f, m1v = -1e30f;
        #pragma unroll
        for (int nt = 0; nt < 16; nt++) {
            float2 a01 = h2f2(acc[mt][nt][0]), a23 = h2f2(acc[mt][nt][1]);
            m0v = fmaxf(m0v, fmaxf(a01.x, a01.y));
            m1v = fmaxf(m1v, fmaxf(a23.x, a23.y));
        }
        m0v = fmaxf(m0v, __shfl_xor_sync(0xffffffffu, m0v, 1));
        m0v = fmaxf(m0v, __shfl_xor_sync(0xffffffffu, m0v, 2));
        m1v = fmaxf(m1v, __shfl_xor_sync(0xffffffffu, m1v, 1));
        m1v = fmaxf(m1v, __shfl_xor_sync(0xffffffffu, m1v, 2));
        rmax[mt][0] = m0v; rmax[mt][1] = m1v;
    }
    if (qt == 0) {
        #pragma unroll
        for (int mt = 0; mt < 2; mt++) {
            red[(wq * 32 + mt * 16 + quad) * 8 + wn]     = rmax[mt][0];
            red[(wq * 32 + mt * 16 + 8 + quad) * 8 + wn] = rmax[mt][1];
        }
    }
    __syncthreads();
    float M[2][2];
    #pragma unroll
    for (int mt = 0; mt < 2; mt++)
        #pragma unroll
        for (int h = 0; h < 2; h++) {
            float m = -1e30f;
            #pragma unroll
            for (int w8 = 0; w8 < 8; w8++)
                m = fmaxf(m, red[(wq * 32 + mt * 16 + h * 8 + quad) * 8 + w8]);
            M[mt][h] = m;
        }

    float rsum[2][2] = {{0.f, 0.f}, {0.f, 0.f}};
    #pragma unroll
    for (int mt = 0; mt < 2; mt++)
        #pragma unroll
        for (int nt = 0; nt < 16; nt++) {
            float2 a01 = h2f2(acc[mt][nt][0]), a23 = h2f2(acc[mt][nt][1]);
            float e0 = __expf(a01.x - M[mt][0]), e1 = __expf(a01.y - M[mt][0]);
            float e2 = __expf(a23.x - M[mt][1]), e3 = __expf(a23.y - M[mt][1]);
            rsum[mt][0] += e0 + e1;
            rsum[mt][1] += e2 + e3;
            acc[mt][nt][0] = f2h2(e0, e1);
            acc[mt][nt][1] = f2h2(e2, e3);
        }
    #pragma unroll
    for (int mt = 0; mt < 2; mt++)
        #pragma unroll
        for (int h = 0; h < 2; h++) {
            rsum[mt][h] += __shfl_xor_sync(0xffffffffu, rsum[mt][h], 1);
            rsum[mt][h] += __shfl_xor_sync(0xffffffffu, rsum[mt][h], 2);
        }
    if (qt == 0) {
        #pragma unroll
        for (int mt = 0; mt < 2; mt++) {
            red2[(wq * 32 + mt * 16 + quad) * 8 + wn]     = rsum[mt][0];
            red2[(wq * 32 + mt * 16 + 8 + quad) * 8 + wn] = rsum[mt][1];
        }
    }
    __syncthreads();
    float inv[2][2];
    #pragma unroll
    for (int mt = 0; mt < 2; mt++)
        #pragma unroll
        for (int h = 0; h < 2; h++) {
            float s = 0.f;
            #pragma unroll
            for (int w8 = 0; w8 < 8; w8++)
                s += red2[(wq * 32 + mt * 16 + h * 8 + quad) * 8 + w8];
            inv[mt][h] = 1.0f / s;
        }

    fp16* P = g_p + (size_t)b * N_ * N_;
    #pragma unroll
    for (int mt = 0; mt < 2; mt++) {
        int r0 = m0 + wq * 32 + mt * 16 + quad;
        #pragma unroll
        for (int nt = 0; nt < 16; nt++) {
            int cc = wn * 128 + nt * 8 + qt * 2;
            float2 e01 = h2f2(acc[mt][nt][0]), e23 = h2f2(acc[mt][nt][1]);
            *reinterpret_cast<uint32_t*>(P + (size_t)r0 * N_ + cc) =
                f2h2(e01.x * inv[mt][0], e01.y * inv[mt][0]);
            *reinterpret_cast<uint32_t*>(P + (size_t)(r0 + 8) * N_ + cc) =
                f2h2(e23.x * inv[mt][1], e23.y * inv[mt][1]);
        }
    }
}

// ---------------------------------------------------------------------------
// 5. PV as O^T: out[b][c][n] = sum_m Vt[b][c][m] * P[b][n][m] + x[b][c][n]
// ---------------------------------------------------------------------------
__global__ __launch_bounds__(256) void pv_kernel(const float* __restrict__ x,
                                                 float* __restrict__ outp) {
    extern __shared__ __align__(16) char dsm[];
    int tid = threadIdx.x;
    int b = blockIdx.z;
    int n0 = blockIdx.x * 128;   // token tile
    int m0 = blockIdx.y * 128;   // channel tile
    const fp16* A  = g_vt + (size_t)b * C_ * N_ + (size_t)m0 * N_;
    const fp16* Bm = g_p  + (size_t)b * N_ * N_ + (size_t)n0 * N_;
    uint32_t acc[2][8][2] = {};
    gemm_ms(A, N_, Bm, N_, N_ / KT, dsm, acc, tid);

    int lane = tid & 31, wid = tid >> 5;
    int wm = wid & 3, wn = wid >> 2;
    int quad = lane >> 2, qt = lane & 3;
    #pragma unroll
    for (int mt = 0; mt < 2; mt++) {
        int cg = m0 + wm * 32 + mt * 16 + quad;
        #pragma unroll
        for (int nt = 0; nt < 8; nt++) {
            int ng = n0 + wn * 64 + nt * 8 + qt * 2;
            size_t base = ((size_t)b * C_ + cg) * N_ + ng;
            float2 c01 = h2f2(acc[mt][nt][0]);
            float2 c23 = h2f2(acc[mt][nt][1]);
            float2 xv = *reinterpret_cast<const float2*>(x + base);
            *reinterpret_cast<float2*>(outp + base) =
                make_float2(c01.x + xv.x, c01.y + xv.y);
            size_t base8 = base + (size_t)8 * N_;
            float2 xv8 = *reinterpret_cast<const float2*>(x + base8);
            *reinterpret_cast<float2*>(outp + base8) =
                make_float2(c23.x + xv8.x, c23.y + xv8.y);
        }
    }
}

// ---------------------------------------------------------------------------
extern "C" void kernel_launch(void* const* d_in, const int* in_sizes, int n_in,
                              void* d_out, int out_size) {
    const float* x     = (const float*)d_in[0];
    const float* Wq    = (const float*)d_in[1];
    const float* bq    = (const float*)d_in[2];
    const float* Wk    = (const float*)d_in[3];
    const float* bk    = (const float*)d_in[4];
    const float* Wv    = (const float*)d_in[5];
    const float* bv    = (const float*)d_in[6];
    const float* gamma = (const float*)d_in[7];
    const float* beta  = (const float*)d_in[8];
    float* out = (float*)d_out;

    cudaFuncSetAttribute(qkv_kernel, cudaFuncAttributeMaxDynamicSharedMemorySize, GEMM_SMEM);
    cudaFuncSetAttribute(pv_kernel, cudaFuncAttributeMaxDynamicSharedMemorySize, GEMM_SMEM);
    cudaFuncSetAttribute(score_softmax_kernel, cudaFuncAttributeMaxDynamicSharedMemorySize, FS_SMEM);

    gn_stats_kernel<<<576, 256>>>(x, Wq, Wk, Wv);
    gn_apply_kernel<<<dim3(8, NG, B_), 256>>>(x, gamma, beta);
    qkv_kernel<<<dim3(2, 8, 3 * B_), 256, GEMM_SMEM>>>(bq, bk, bv);
    score_softmax_kernel<<<dim3(16, B_), 512, FS_SMEM>>>();
    pv_kernel<<<dim3(8, 2, B_), 256, GEMM_SMEM>>>(x, out);
}